// round 15
// baseline (speedup 1.0000x reference)
#include <cuda_runtime.h>
#include <cuda_fp16.h>
#include <cstdint>
#include <math.h>

// Problem constants
#define B_    2
#define T_    2048
#define C_    1024
#define H_    16
#define D_    64
#define DSTD_ 60
#define M_    (B_*T_)   // 4096 rows

// ---------------------------------------------------------------------------
// Scratch (__device__ globals; no allocation allowed)
// ---------------------------------------------------------------------------
__device__ __half g_x16[M_*C_];
__device__ __half g_wa16[3*C_*C_];
__device__ __half g_wp16[C_*C_];
__device__ __half g_y16[M_*C_];
__device__ __half g_q16[B_*H_*T_*D_];   // [B*H, T, D]
__device__ __half g_k16[B_*H_*T_*D_];
__device__ __half g_v16[B_*H_*T_*D_];
__device__ int    g_ctr;                // attention work-queue counter

__device__ __forceinline__ float sigmoidf_(float v) { return 1.0f / (1.0f + __expf(-v)); }

__device__ __forceinline__ uint32_t smem_u32(const void* p) {
    return (uint32_t)__cvta_generic_to_shared(p);
}

__device__ __forceinline__ float ex2_(float x) {
    float r; asm("ex2.approx.f32 %0, %1;" : "=f"(r) : "f"(x)); return r;
}
__device__ __forceinline__ uint32_t ex2h2_(uint32_t x) {
    uint32_t r; asm("ex2.approx.f16x2 %0, %1;" : "=r"(r) : "r"(x)); return r;
}
__device__ __forceinline__ uint32_t packh2_(float x, float y) {
    __half2 h = __floats2half2_rn(x, y);
    return *reinterpret_cast<uint32_t*>(&h);
}

// ---------------------------------------------------------------------------
// warp-mma helpers (baseline PTX ISA — safe for compute_103 target)
// ---------------------------------------------------------------------------
__device__ __forceinline__ void ldsm4(uint32_t* r, uint32_t addr) {
    asm volatile("ldmatrix.sync.aligned.m8n8.x4.shared.b16 {%0,%1,%2,%3}, [%4];"
        : "=r"(r[0]), "=r"(r[1]), "=r"(r[2]), "=r"(r[3]) : "r"(addr));
}

__device__ __forceinline__ void ldsm4t(uint32_t* r, uint32_t addr) {
    asm volatile("ldmatrix.sync.aligned.m8n8.x4.trans.shared.b16 {%0,%1,%2,%3}, [%4];"
        : "=r"(r[0]), "=r"(r[1]), "=r"(r[2]), "=r"(r[3]) : "r"(addr));
}

__device__ __forceinline__ void mma_f16(float* c, const uint32_t* a, uint32_t b0, uint32_t b1) {
    asm volatile("mma.sync.aligned.m16n8k16.row.col.f32.f16.f16.f32 "
        "{%0,%1,%2,%3}, {%4,%5,%6,%7}, {%8,%9}, {%0,%1,%2,%3};"
        : "+f"(c[0]), "+f"(c[1]), "+f"(c[2]), "+f"(c[3])
        : "r"(a[0]), "r"(a[1]), "r"(a[2]), "r"(a[3]), "r"(b0), "r"(b1));
}

__device__ __forceinline__ void cp16(uint32_t saddr, const void* gaddr) {
    asm volatile("cp.async.cg.shared.global [%0], [%1], 16;" :: "r"(saddr), "l"(gaddr));
}

// ---------------------------------------------------------------------------
// fused fp32 -> fp16 convert for x, W_attn, W_proj (one launch)
// ---------------------------------------------------------------------------
#define NX4_  (M_*C_/4)       // 1048576
#define NWA4_ (3*C_*C_/4)     // 786432
#define NWP4_ (C_*C_/4)       // 262144
#define NTOT4_ (NX4_+NWA4_+NWP4_)

__global__ __launch_bounds__(256) void conv_kernel(
    const float4* __restrict__ x, const float4* __restrict__ wa, const float4* __restrict__ wp)
{
    int i = blockIdx.x * blockDim.x + threadIdx.x;
    if (i >= NTOT4_) return;
    const float4* s; uint2* d; int o;
    if (i < NX4_)              { s = x;  d = (uint2*)g_x16;  o = i; }
    else if (i < NX4_ + NWA4_) { s = wa; d = (uint2*)g_wa16; o = i - NX4_; }
    else                       { s = wp; d = (uint2*)g_wp16; o = i - NX4_ - NWA4_; }
    float4 v = s[o];
    d[o] = make_uint2(packh2_(v.x, v.y), packh2_(v.z, v.w));
}

// ---------------------------------------------------------------------------
// fp16 warp-MMA GEMM (NT): C[m,n] = sum_k A[m,k]*B[n,k].
// R15: CTA tile 128(M) x 64(N), 128 threads, 4 warps as 2(m) x 2(n) ->
// 64x32 per warp. BK=32, 4-stage ring, acc-major ks-chains (R9 order ->
// bitwise-identical per-element accumulation). SMEM/stage = 15360 B,
// total 61440 -> 3 CTAs/SM (3 warps/SMSP) and finer wave granularity:
// QKV 1536 CTAs (3.46 waves of 444), proj 512 CTAs (1.15 waves).
// mode 0: scatter q/k/v fp16 with head scaling; mode 1: plain fp32 write.
// ---------------------------------------------------------------------------
#define GS_A    10240          // A: 128 rows * 80 B
#define GS_B    5120           // B:  64 rows * 80 B
#define GS_STG  (GS_A+GS_B)    // 15360
#define GS_SMEM (4*GS_STG)     // 61440

// scale const: D^-1/4 * sqrt(log2(e))
#define QK_SCALE 0.42466089786070306f

__device__ __forceinline__ void load_a32(
    uint32_t sdst, const __half* __restrict__ src, int Kdim, int k0, int tid)
{
#pragma unroll
    for (int p = 0; p < 4; p++) {
        int idx = tid + p * 128;        // 0..511
        int row = idx >> 2;             // 0..127
        int c8  = (idx & 3) * 8;
        cp16(sdst + (uint32_t)(row * 80 + c8 * 2), src + (size_t)row * Kdim + k0 + c8);
    }
}
__device__ __forceinline__ void load_b32(
    uint32_t sdst, const __half* __restrict__ src, int Kdim, int k0, int tid)
{
#pragma unroll
    for (int p = 0; p < 2; p++) {
        int idx = tid + p * 128;        // 0..255
        int row = idx >> 2;             // 0..63
        int c8  = (idx & 3) * 8;
        cp16(sdst + (uint32_t)(row * 80 + c8 * 2), src + (size_t)row * Kdim + k0 + c8);
    }
}

__global__ void __launch_bounds__(128, 3) gemm_f16_kernel(
    const __half* __restrict__ A, const __half* __restrict__ Bm,
    float* __restrict__ Cout, int Ndim, int Kdim, int mode,
    const float* __restrict__ w_std, const float* __restrict__ w_rec,
    const float* __restrict__ skip_std, const float* __restrict__ skip_low)
{
    extern __shared__ char smem[];
    const uint32_t sbase = smem_u32(smem);
    const int tid  = threadIdx.x;
    const int wid  = tid >> 5;
    const int lane = tid & 31;
    const int warp_m = wid >> 1;        // 0..1 (64 rows each)
    const int warp_n = wid & 1;         // 0..1 (32 cols each)

    const int m0 = blockIdx.y * 128;
    const int n0 = blockIdx.x * 64;

    const int lr = lane & 7, sel = lane >> 3;
    const int rowA = ((sel & 1) ? 8 : 0) + lr;
    const int kbA  = (sel & 2) ? 16 : 0;
    const int rowB = ((sel & 2) ? 8 : 0) + lr;
    const int kbB  = (sel & 1) ? 16 : 0;

    const uint32_t aoff = (uint32_t)((warp_m * 64 + rowA) * 80 + kbA);
    const uint32_t boff = (uint32_t)(GS_A + (warp_n * 32 + rowB) * 80 + kbB);

    const __half* Ag = A  + (size_t)m0 * Kdim;
    const __half* Bg = Bm + (size_t)n0 * Kdim;

    float acc[4][4][4];
#pragma unroll
    for (int a = 0; a < 4; a++)
#pragma unroll
        for (int b = 0; b < 4; b++)
#pragma unroll
            for (int c = 0; c < 4; c++) acc[a][b][c] = 0.0f;

    const int nch = Kdim >> 5;          // BK=32

#pragma unroll
    for (int pc = 0; pc < 3; pc++) {
        const uint32_t st = sbase + (uint32_t)pc * GS_STG;
        load_a32(st,        Ag, Kdim, pc << 5, tid);
        load_b32(st + GS_A, Bg, Kdim, pc << 5, tid);
        asm volatile("cp.async.commit_group;" ::: "memory");
    }

    for (int i = 0; i < nch; i++) {
        if (i + 2 < nch)      asm volatile("cp.async.wait_group 2;" ::: "memory");
        else if (i + 1 < nch) asm volatile("cp.async.wait_group 1;" ::: "memory");
        else                  asm volatile("cp.async.wait_group 0;" ::: "memory");
        __syncthreads();
        if (i + 3 < nch) {
            const uint32_t st = sbase + (uint32_t)((i + 3) & 3) * GS_STG;
            load_a32(st,        Ag, Kdim, (i + 3) << 5, tid);
            load_b32(st + GS_A, Bg, Kdim, (i + 3) << 5, tid);
            asm volatile("cp.async.commit_group;" ::: "memory");
        }
        const uint32_t sb = sbase + (uint32_t)(i & 3) * GS_STG;

        // both ks frag sets, then acc-major dependent chains of 2 (R9 order)
        uint32_t a4[2][4][4], b4[2][2][4];
#pragma unroll
        for (int ks = 0; ks < 2; ks++) {
#pragma unroll
            for (int mt = 0; mt < 4; mt++)
                ldsm4(a4[ks][mt], sb + aoff + (uint32_t)(mt * 1280 + ks * 32));
#pragma unroll
            for (int np = 0; np < 2; np++)
                ldsm4(b4[ks][np], sb + boff + (uint32_t)(np * 1280 + ks * 32));
        }
#pragma unroll
        for (int mt = 0; mt < 4; mt++)
#pragma unroll
            for (int nt = 0; nt < 4; nt++) {
                const int np = nt >> 1, h = (nt & 1) * 2;
                mma_f16(acc[mt][nt], a4[0][mt], b4[0][np][h], b4[0][np][h + 1]);
                mma_f16(acc[mt][nt], a4[1][mt], b4[1][np][h], b4[1][np][h + 1]);
            }
    }

    // ----------------------------- epilogue --------------------------------
    const int lr4 = lane >> 2;
    const int lc2 = (lane & 3) * 2;

    if (mode == 0) {
        const int nb  = n0 + warp_n * 32;       // 32-aligned: sec & head constant
        const int sec = nb >> 10;               // 0=q 1=k 2=v
        const int f   = nb & 1023;
        const int h   = f >> 6;
        float gstd = 1.0f, grec = 1.0f;
        if (sec < 2) {
            const float ss = sigmoidf_(skip_std[0]);
            const float sl = sigmoidf_(skip_low[0]);
            gstd = sqrtf(fmaxf(w_std[h] * ss, 1e-8f)) * QK_SCALE;
            grec = sqrtf(fmaxf(w_rec[h] * sl, 1e-8f)) * QK_SCALE;
        }
        __half* dst = (sec == 0) ? g_q16 : (sec == 1) ? g_k16 : g_v16;
#pragma unroll
        for (int mt = 0; mt < 4; mt++) {
            const int r0 = m0 + warp_m * 64 + mt * 16 + lr4;
#pragma unroll
            for (int half = 0; half < 2; half++) {
                const int m = r0 + half * 8;
                const int b = m >> 11;
                const int t = m & (T_ - 1);
                const size_t base = (((size_t)(b * H_ + h)) * T_ + t) * D_;
#pragma unroll
                for (int nt = 0; nt < 4; nt++) {
                    const int d = (f & 63) + nt * 8 + lc2;
                    const float s0 = (sec < 2) ? ((d     < DSTD_) ? gstd : grec) : 1.0f;
                    const float s1 = (sec < 2) ? ((d + 1 < DSTD_) ? gstd : grec) : 1.0f;
                    uint32_t hv = packh2_(acc[mt][nt][half*2 + 0] * s0,
                                          acc[mt][nt][half*2 + 1] * s1);
                    *(uint32_t*)&dst[base + d] = hv;
                }
            }
        }
    } else {
#pragma unroll
        for (int mt = 0; mt < 4; mt++) {
            const int r0 = m0 + warp_m * 64 + mt * 16 + lr4;
#pragma unroll
            for (int half = 0; half < 2; half++) {
                const int m = r0 + half * 8;
#pragma unroll
                for (int nt = 0; nt < 4; nt++) {
                    const int col = n0 + warp_n * 32 + nt * 8 + lc2;
                    float2 o;
                    o.x = acc[mt][nt][half * 2 + 0];
                    o.y = acc[mt][nt][half * 2 + 1];
                    *(float2*)&Cout[(size_t)m * Ndim + col] = o;
                }
            }
        }
    }
}

// ---------------------------------------------------------------------------
// fp16 tensor-core causal flash attention + reciprocal mix. (R13 — best)
// Persistent 296-CTA grid, heavy-first atomic work queue, 64-wide KV rounds,
// 3-stage ring, conditional exact rescale, l-via-MMA (all-ones B frag).
// ---------------------------------------------------------------------------
#define NQT_    (T_/128)            // 16 q-tiles
#define NTILE_  (NQT_*B_*H_)        // 512 work items
#define AQ_B    18432               // Q region: 128*144
#define AT_T    9216                // one 64x144 tile
#define AT_STG2 (2*AT_T)            // K+V stage
#define AT_SMEM (AQ_B + 3*AT_STG2)  // 73728

__device__ __forceinline__ void attn_load_kv16(
    uint32_t sb, int k0, int tid,
    const __half* __restrict__ Kg, const __half* __restrict__ Vg)
{
#pragma unroll
    for (int p = 0; p < 2; p++) {
        int idx = tid + p * 256;    // 0..511
        int row = idx >> 3;         // 0..63
        int c8  = (idx & 7) * 8;
        cp16(sb + (uint32_t)(row * 144 + c8 * 2),        Kg + (size_t)(k0 + row) * 64 + c8);
        cp16(sb + (uint32_t)(AT_T + row * 144 + c8 * 2), Vg + (size_t)(k0 + row) * 64 + c8);
    }
}

__global__ void __launch_bounds__(256, 2) attn_f16_kernel(const float* __restrict__ rwr_alpha)
{
    extern __shared__ char smem[];
    __shared__ int s_tile;
    const uint32_t sbase = smem_u32(smem);
    const int tid  = threadIdx.x;
    const int wid  = tid >> 5;
    const int lane = tid & 31;

    const int lr = lane & 7, sel = lane >> 3;
    const int rowA = ((sel & 1) ? 8 : 0) + lr;
    const int kbA  = (sel & 2) ? 16 : 0;
    const int rowB = ((sel & 2) ? 8 : 0) + lr;
    const int kbB  = (sel & 1) ? 16 : 0;
    const int g  = lane >> 2;
    const int t2 = (lane & 3) * 2;
    const uint32_t ones = 0x3C003C00u;   // all-ones B frag: every col = rowsum

    for (;;) {
        __syncthreads();                 // prior tile fully done; s_tile free
        if (tid == 0) s_tile = atomicAdd(&g_ctr, 1);
        __syncthreads();
        const int idx = s_tile;
        if (idx >= NTILE_) break;

        // heavy-first: all 32 heads' qt=15 tiles, then qt=14, ...
        const int qt = (NQT_ - 1) - (idx >> 5);
        const int bh = idx & 31;
        const int q0 = qt * 128;
        const int qw = q0 + wid * 16;
        const int nkt = 2 * qt + 2;

        const size_t hoff = (size_t)bh * (T_ * D_);
        const __half* Qg = g_q16 + hoff;
        const __half* Kg = g_k16 + hoff;
        const __half* Vg = g_v16 + hoff;

        const int h = bh & (H_ - 1);
        const int b = bh >> 4;
        const float alpha = fminf(fmaxf(rwr_alpha[h], 0.0f), 0.5f);
        const float om = 1.0f - alpha;

        // Q tile load (group 0)
#pragma unroll
        for (int p = 0; p < 4; p++) {
            int i2 = tid + p * 256;
            int row = i2 >> 3;
            int c8  = (i2 & 7) * 8;
            cp16(sbase + (uint32_t)(row * 144 + c8 * 2), Qg + (size_t)(q0 + row) * 64 + c8);
        }
        asm volatile("cp.async.commit_group;" ::: "memory");

        attn_load_kv16(sbase + AQ_B,           0,  tid, Kg, Vg);
        asm volatile("cp.async.commit_group;" ::: "memory");
        attn_load_kv16(sbase + AQ_B + AT_STG2, 64, tid, Kg, Vg);
        asm volatile("cp.async.commit_group;" ::: "memory");

        asm volatile("cp.async.wait_group 2;" ::: "memory");
        __syncthreads();

        uint32_t qh[4][4];
        {
            const uint32_t qaddr = sbase + (uint32_t)((wid * 16 + rowA) * 144 + kbA);
#pragma unroll
            for (int kc = 0; kc < 4; kc++) ldsm4(qh[kc], qaddr + (uint32_t)(kc * 32));
        }

        float O[8][4];
        float Ol[4] = {0.0f, 0.0f, 0.0f, 0.0f};
        float mrow[2] = {-1e30f, -1e30f};
#pragma unroll
        for (int nt = 0; nt < 8; nt++)
#pragma unroll
            for (int c = 0; c < 4; c++) O[nt][c] = 0.0f;

        for (int kt = 0; kt < nkt; kt++) {
            if (kt + 1 < nkt) asm volatile("cp.async.wait_group 1;" ::: "memory");
            else              asm volatile("cp.async.wait_group 0;" ::: "memory");
            __syncthreads();
            if (kt + 2 < nkt) {
                attn_load_kv16(sbase + AQ_B + (uint32_t)((kt + 2) % 3) * AT_STG2,
                               (kt + 2) * 64, tid, Kg, Vg);
                asm volatile("cp.async.commit_group;" ::: "memory");
            }

            const uint32_t sb = sbase + AQ_B + (uint32_t)(kt % 3) * AT_STG2;
            const int k0 = kt * 64;

            if (k0 <= qw + 15) {
                // ---- S = Q.K^T (scores in log2 domain) ----
                float S[8][4];
#pragma unroll
                for (int nt = 0; nt < 8; nt++)
#pragma unroll
                    for (int c = 0; c < 4; c++) S[nt][c] = 0.0f;

#pragma unroll
                for (int np = 0; np < 4; np++) {
                    const uint32_t kb_ = sb + (uint32_t)((np * 16 + rowB) * 144 + kbB);
#pragma unroll
                    for (int kc = 0; kc < 4; kc++) {
                        uint32_t k4[4];
                        ldsm4(k4, kb_ + (uint32_t)(kc * 32));
                        mma_f16(S[2*np],     qh[kc], k4[0], k4[1]);
                        mma_f16(S[2*np + 1], qh[kc], k4[2], k4[3]);
                    }
                }

                // ---- causal mask ----
                if (k0 + 63 > qw) {
#pragma unroll
                    for (int nt = 0; nt < 8; nt++) {
                        const int colb = k0 + nt * 8 + t2;
#pragma unroll
                        for (int c = 0; c < 2; c++) {
                            if (colb + c > qw + g)     S[nt][c]     = -1e30f;
                            if (colb + c > qw + g + 8) S[nt][2 + c] = -1e30f;
                        }
                    }
                }

                // ---- row max + CONDITIONAL rescale ----
                float mn[2];
#pragma unroll
                for (int r = 0; r < 2; r++) {
                    float mx = -1e30f;
#pragma unroll
                    for (int nt = 0; nt < 8; nt++)
                        mx = fmaxf(mx, fmaxf(S[nt][2*r], S[nt][2*r + 1]));
                    mx = fmaxf(mx, __shfl_xor_sync(0xffffffffu, mx, 1));
                    mx = fmaxf(mx, __shfl_xor_sync(0xffffffffu, mx, 2));
                    mn[r] = fmaxf(mrow[r], mx);
                }
                // skip is EXACT when no row max rose (corr == ex2(0) == 1)
                if (__any_sync(0xffffffffu,
                               (mn[0] > mrow[0]) | (mn[1] > mrow[1]))) {
#pragma unroll
                    for (int r = 0; r < 2; r++) {
                        const float corr = ex2_(mrow[r] - mn[r]);
                        mrow[r] = mn[r];
#pragma unroll
                        for (int nt = 0; nt < 8; nt++) {
                            O[nt][2*r]     *= corr;
                            O[nt][2*r + 1] *= corr;
                        }
                        Ol[2*r] *= corr;
                    }
                }

                // ---- P = exp2(S - m) in f16x2 ----
                uint32_t pa[4][4];
#pragma unroll
                for (int kc = 0; kc < 4; kc++) {
                    pa[kc][0] = ex2h2_(packh2_(S[2*kc][0]   - mn[0], S[2*kc][1]   - mn[0]));
                    pa[kc][1] = ex2h2_(packh2_(S[2*kc][2]   - mn[1], S[2*kc][3]   - mn[1]));
                    pa[kc][2] = ex2h2_(packh2_(S[2*kc+1][0] - mn[0], S[2*kc+1][1] - mn[0]));
                    pa[kc][3] = ex2h2_(packh2_(S[2*kc+1][2] - mn[1], S[2*kc+1][3] - mn[1]));
                }

                // ---- O += P.V ; l += P.ones (same P, fp32 accum) ----
#pragma unroll
                for (int kc = 0; kc < 4; kc++) {
                    mma_f16(Ol, pa[kc], ones, ones);
#pragma unroll
                    for (int nd = 0; nd < 4; nd++) {
                        uint32_t v4[4];
                        const uint32_t vaddr = sb + (uint32_t)(AT_T
                            + (kc * 16 + (lane & 15)) * 144
                            + nd * 32 + ((lane & 16) ? 16 : 0));
                        ldsm4t(v4, vaddr);
                        mma_f16(O[2*nd],     pa[kc], v4[0], v4[1]);
                        mma_f16(O[2*nd + 1], pa[kc], v4[2], v4[3]);
                    }
                }
            }
        }

        // ---- epilogue: normalize, reciprocal mix, write y fp16 ----
#pragma unroll
        for (int r = 0; r < 2; r++) {
            const int q = qw + g + r * 8;
            const float inv = 1.0f / Ol[2*r];
            const size_t vrow = (size_t)q * 64;
            const size_t orow = ((size_t)(b * T_ + q)) * C_ + h * 64;
#pragma unroll
            for (int nt = 0; nt < 8; nt++) {
                const int d = nt * 8 + t2;
                const uint32_t uv = *(const uint32_t*)&Vg[vrow + d];
                const float2 fv = __half22float2(*(const __half2*)&uv);
                const float y0 = om * (O[nt][2*r]     * inv) + alpha * fv.x;
                const float y1 = om * (O[nt][2*r + 1] * inv) + alpha * fv.y;
                *(uint32_t*)&g_y16[orow + d] = packh2_(y0, y1);
            }
        }
    }
}

// ---------------------------------------------------------------------------
extern "C" void kernel_launch(void* const* d_in, const int* in_sizes, int n_in,
                              void* d_out, int out_size)
{
    const float* x         = (const float*)d_in[0];
    const float* W_attn    = (const float*)d_in[1];
    const float* W_proj    = (const float*)d_in[2];
    const float* w_std     = (const float*)d_in[3];
    const float* w_rec     = (const float*)d_in[4];
    const float* skip_std  = (const float*)d_in[5];
    const float* skip_low  = (const float*)d_in[6];
    const float* rwr_alpha = (const float*)d_in[7];
    float* out = (float*)d_out;

    static void *p_x16 = nullptr, *p_wa16, *p_wp16, *p_y16, *p_ctr;
    if (!p_x16) {
        cudaGetSymbolAddress(&p_x16,  g_x16);
        cudaGetSymbolAddress(&p_wa16, g_wa16);
        cudaGetSymbolAddress(&p_wp16, g_wp16);
        cudaGetSymbolAddress(&p_y16,  g_y16);
        cudaGetSymbolAddress(&p_ctr,  g_ctr);
    }

    static bool attr_set = false;
    if (!attr_set) {
        cudaFuncSetAttribute(gemm_f16_kernel, cudaFuncAttributeMaxDynamicSharedMemorySize, GS_SMEM);
        cudaFuncSetAttribute(attn_f16_kernel, cudaFuncAttributeMaxDynamicSharedMemorySize, AT_SMEM);
        attr_set = true;
    }

    // 1. fused fp32 -> fp16 conversion (x, W_attn, W_proj)
    conv_kernel<<<(NTOT4_ + 255) / 256, 256>>>(
        (const float4*)x, (const float4*)W_attn, (const float4*)W_proj);

    // 2. QKV GEMM: 128x64 tiles -> 1536 CTAs (3 CTAs/SM, 3.46 waves)
    gemm_f16_kernel<<<dim3(3*C_/64, M_/128), 128, GS_SMEM>>>(
        (const __half*)p_x16, (const __half*)p_wa16,
        nullptr, 3*C_, C_, 0, w_std, w_rec, skip_std, skip_low);

    // 3. attention: persistent 296-CTA grid, heavy-first atomic work queue
    cudaMemsetAsync(p_ctr, 0, sizeof(int));
    attn_f16_kernel<<<296, 256, AT_SMEM>>>(rwr_alpha);

    // 4. output projection: 128x64 tiles -> 512 CTAs (1.15 waves)
    gemm_f16_kernel<<<dim3(C_/64, M_/128), 128, GS_SMEM>>>(
        (const __half*)p_y16, (const __half*)p_wp16,
        out, C_, C_, 1, nullptr, nullptr, nullptr, nullptr);
}

// round 16
// speedup vs baseline: 1.1230x; 1.1230x over previous
#include <cuda_runtime.h>
#include <cuda_fp16.h>
#include <cstdint>
#include <math.h>

// Problem constants
#define B_    2
#define T_    2048
#define C_    1024
#define H_    16
#define D_    64
#define DSTD_ 60
#define M_    (B_*T_)   // 4096 rows

// ---------------------------------------------------------------------------
// Scratch (__device__ globals; no allocation allowed)
// ---------------------------------------------------------------------------
__device__ __half g_x16[M_*C_];
__device__ __half g_wa16[3*C_*C_];
__device__ __half g_wp16[C_*C_];
__device__ __half g_y16[M_*C_];
__device__ __half g_q16[B_*H_*T_*D_];   // [B*H, T, D]
__device__ __half g_k16[B_*H_*T_*D_];
__device__ __half g_v16[B_*H_*T_*D_];
__device__ int    g_ctr;                // attention work-queue counter (self-resetting)

__device__ __forceinline__ float sigmoidf_(float v) { return 1.0f / (1.0f + __expf(-v)); }

__device__ __forceinline__ uint32_t smem_u32(const void* p) {
    return (uint32_t)__cvta_generic_to_shared(p);
}

__device__ __forceinline__ float ex2_(float x) {
    float r; asm("ex2.approx.f32 %0, %1;" : "=f"(r) : "f"(x)); return r;
}
__device__ __forceinline__ uint32_t ex2h2_(uint32_t x) {
    uint32_t r; asm("ex2.approx.f16x2 %0, %1;" : "=r"(r) : "r"(x)); return r;
}
__device__ __forceinline__ uint32_t packh2_(float x, float y) {
    __half2 h = __floats2half2_rn(x, y);
    return *reinterpret_cast<uint32_t*>(&h);
}

// ---------------------------------------------------------------------------
// warp-mma helpers (baseline PTX ISA — safe for compute_103 target)
// ---------------------------------------------------------------------------
__device__ __forceinline__ void ldsm4(uint32_t* r, uint32_t addr) {
    asm volatile("ldmatrix.sync.aligned.m8n8.x4.shared.b16 {%0,%1,%2,%3}, [%4];"
        : "=r"(r[0]), "=r"(r[1]), "=r"(r[2]), "=r"(r[3]) : "r"(addr));
}

__device__ __forceinline__ void ldsm4t(uint32_t* r, uint32_t addr) {
    asm volatile("ldmatrix.sync.aligned.m8n8.x4.trans.shared.b16 {%0,%1,%2,%3}, [%4];"
        : "=r"(r[0]), "=r"(r[1]), "=r"(r[2]), "=r"(r[3]) : "r"(addr));
}

__device__ __forceinline__ void mma_f16(float* c, const uint32_t* a, uint32_t b0, uint32_t b1) {
    asm volatile("mma.sync.aligned.m16n8k16.row.col.f32.f16.f16.f32 "
        "{%0,%1,%2,%3}, {%4,%5,%6,%7}, {%8,%9}, {%0,%1,%2,%3};"
        : "+f"(c[0]), "+f"(c[1]), "+f"(c[2]), "+f"(c[3])
        : "r"(a[0]), "r"(a[1]), "r"(a[2]), "r"(a[3]), "r"(b0), "r"(b1));
}

__device__ __forceinline__ void cp16(uint32_t saddr, const void* gaddr) {
    asm volatile("cp.async.cg.shared.global [%0], [%1], 16;" :: "r"(saddr), "l"(gaddr));
}

// ---------------------------------------------------------------------------
// fused fp32 -> fp16 convert (grid-stride, ~7 float4 per thread for MLP)
// ---------------------------------------------------------------------------
#define NX4_  (M_*C_/4)       // 1048576
#define NWA4_ (3*C_*C_/4)     // 786432
#define NWP4_ (C_*C_/4)       // 262144
#define NTOT4_ (NX4_+NWA4_+NWP4_)
#define CONV_BLOCKS 1184      // 296 resident CTAs * 4

__global__ __launch_bounds__(256) void conv_kernel(
    const float4* __restrict__ x, const float4* __restrict__ wa, const float4* __restrict__ wp)
{
    const int stride = CONV_BLOCKS * 256;
    for (int i = blockIdx.x * 256 + threadIdx.x; i < NTOT4_; i += stride) {
        const float4* s; uint2* d; int o;
        if (i < NX4_)              { s = x;  d = (uint2*)g_x16;  o = i; }
        else if (i < NX4_ + NWA4_) { s = wa; d = (uint2*)g_wa16; o = i - NX4_; }
        else                       { s = wp; d = (uint2*)g_wp16; o = i - NX4_ - NWA4_; }
        float4 v = s[o];
        d[o] = make_uint2(packh2_(v.x, v.y), packh2_(v.z, v.w));
    }
}

// ---------------------------------------------------------------------------
// fp16 warp-MMA GEMM (NT) — R13/R9 config (measured best: 44.8% tensor):
// CTA 128x128, 128 threads, 2x2 warps of 64x64, BK=32, 4-stage ring,
// acc-major dependent chains of 2.
// ---------------------------------------------------------------------------
#define GS_OP   10240          // 128 rows * 80 B
#define GS_STG  (2*GS_OP)      // 20480 (A + B)
#define GS_SMEM (4*GS_STG)     // 81920

// scale const: D^-1/4 * sqrt(log2(e))
#define QK_SCALE 0.42466089786070306f

__device__ __forceinline__ void load_op32(
    uint32_t sdst, const __half* __restrict__ src, int Kdim, int k0, int tid)
{
#pragma unroll
    for (int p = 0; p < 4; p++) {
        int idx = tid + p * 128;        // 0..511
        int row = idx >> 2;             // 0..127
        int c8  = (idx & 3) * 8;        // half col 0..24
        cp16(sdst + (uint32_t)(row * 80 + c8 * 2), src + (size_t)row * Kdim + k0 + c8);
    }
}

__global__ void __launch_bounds__(128, 2) gemm_f16_kernel(
    const __half* __restrict__ A, const __half* __restrict__ Bm,
    float* __restrict__ Cout, int Ndim, int Kdim, int mode,
    const float* __restrict__ w_std, const float* __restrict__ w_rec,
    const float* __restrict__ skip_std, const float* __restrict__ skip_low)
{
    extern __shared__ char smem[];
    const uint32_t sbase = smem_u32(smem);
    const int tid  = threadIdx.x;
    const int wid  = tid >> 5;
    const int lane = tid & 31;
    const int warp_m = wid >> 1;        // 0..1
    const int warp_n = wid & 1;         // 0..1

    const int m0 = blockIdx.y * 128;
    const int n0 = blockIdx.x * 128;

    const int lr = lane & 7, sel = lane >> 3;
    const int rowA = ((sel & 1) ? 8 : 0) + lr;
    const int kbA  = (sel & 2) ? 16 : 0;
    const int rowB = ((sel & 2) ? 8 : 0) + lr;
    const int kbB  = (sel & 1) ? 16 : 0;

    const uint32_t aoff = (uint32_t)((warp_m * 64 + rowA) * 80 + kbA);
    const uint32_t boff = (uint32_t)(GS_OP + (warp_n * 64 + rowB) * 80 + kbB);

    const __half* Ag = A  + (size_t)m0 * Kdim;
    const __half* Bg = Bm + (size_t)n0 * Kdim;

    float acc[4][8][4];
#pragma unroll
    for (int a = 0; a < 4; a++)
#pragma unroll
        for (int b = 0; b < 8; b++)
#pragma unroll
            for (int c = 0; c < 4; c++) acc[a][b][c] = 0.0f;

    const int nch = Kdim >> 5;          // BK=32

#pragma unroll
    for (int pc = 0; pc < 3; pc++) {
        const uint32_t st = sbase + (uint32_t)pc * GS_STG;
        load_op32(st,         Ag, Kdim, pc << 5, tid);
        load_op32(st + GS_OP, Bg, Kdim, pc << 5, tid);
        asm volatile("cp.async.commit_group;" ::: "memory");
    }

    for (int i = 0; i < nch; i++) {
        if (i + 2 < nch)      asm volatile("cp.async.wait_group 2;" ::: "memory");
        else if (i + 1 < nch) asm volatile("cp.async.wait_group 1;" ::: "memory");
        else                  asm volatile("cp.async.wait_group 0;" ::: "memory");
        __syncthreads();
        if (i + 3 < nch) {
            const uint32_t st = sbase + (uint32_t)((i + 3) & 3) * GS_STG;
            load_op32(st,         Ag, Kdim, (i + 3) << 5, tid);
            load_op32(st + GS_OP, Bg, Kdim, (i + 3) << 5, tid);
            asm volatile("cp.async.commit_group;" ::: "memory");
        }
        const uint32_t sb = sbase + (uint32_t)(i & 3) * GS_STG;

        uint32_t a4[2][4][4], b4[2][4][4];
#pragma unroll
        for (int ks = 0; ks < 2; ks++) {
#pragma unroll
            for (int mt = 0; mt < 4; mt++)
                ldsm4(a4[ks][mt], sb + aoff + (uint32_t)(mt * 1280 + ks * 32));
#pragma unroll
            for (int np = 0; np < 4; np++)
                ldsm4(b4[ks][np], sb + boff + (uint32_t)(np * 1280 + ks * 32));
        }
#pragma unroll
        for (int mt = 0; mt < 4; mt++)
#pragma unroll
            for (int nt = 0; nt < 8; nt++) {
                const int np = nt >> 1, h = (nt & 1) * 2;
                mma_f16(acc[mt][nt], a4[0][mt], b4[0][np][h], b4[0][np][h + 1]);
                mma_f16(acc[mt][nt], a4[1][mt], b4[1][np][h], b4[1][np][h + 1]);
            }
    }

    const int lr4 = lane >> 2;
    const int lc2 = (lane & 3) * 2;

    if (mode == 0) {
        const int nb  = n0 + warp_n * 64;
        const int sec = nb >> 10;
        const int f   = nb & 1023;
        const int h   = f >> 6;
        float gstd = 1.0f, grec = 1.0f;
        if (sec < 2) {
            const float ss = sigmoidf_(skip_std[0]);
            const float sl = sigmoidf_(skip_low[0]);
            gstd = sqrtf(fmaxf(w_std[h] * ss, 1e-8f)) * QK_SCALE;
            grec = sqrtf(fmaxf(w_rec[h] * sl, 1e-8f)) * QK_SCALE;
        }
        __half* dst = (sec == 0) ? g_q16 : (sec == 1) ? g_k16 : g_v16;
#pragma unroll
        for (int mt = 0; mt < 4; mt++) {
            const int r0 = m0 + warp_m * 64 + mt * 16 + lr4;
#pragma unroll
            for (int half = 0; half < 2; half++) {
                const int m = r0 + half * 8;
                const int b = m >> 11;
                const int t = m & (T_ - 1);
                const size_t base = (((size_t)(b * H_ + h)) * T_ + t) * D_;
#pragma unroll
                for (int nt = 0; nt < 8; nt++) {
                    const int d = nt * 8 + lc2;
                    const float s0 = (sec < 2) ? ((d     < DSTD_) ? gstd : grec) : 1.0f;
                    const float s1 = (sec < 2) ? ((d + 1 < DSTD_) ? gstd : grec) : 1.0f;
                    uint32_t hv = packh2_(acc[mt][nt][half*2 + 0] * s0,
                                          acc[mt][nt][half*2 + 1] * s1);
                    *(uint32_t*)&dst[base + d] = hv;
                }
            }
        }
    } else {
#pragma unroll
        for (int mt = 0; mt < 4; mt++) {
            const int r0 = m0 + warp_m * 64 + mt * 16 + lr4;
#pragma unroll
            for (int half = 0; half < 2; half++) {
                const int m = r0 + half * 8;
#pragma unroll
                for (int nt = 0; nt < 8; nt++) {
                    const int col = n0 + warp_n * 64 + nt * 8 + lc2;
                    float2 o;
                    o.x = acc[mt][nt][half * 2 + 0];
                    o.y = acc[mt][nt][half * 2 + 1];
                    *(float2*)&Cout[(size_t)m * Ndim + col] = o;
                }
            }
        }
    }
}

// ---------------------------------------------------------------------------
// fp16 tensor-core causal flash attention + reciprocal mix. (R13 — best)
// Persistent 296-CTA grid, heavy-first atomic work queue, 64-wide KV rounds,
// 3-stage ring, conditional exact rescale, l-via-MMA (all-ones B frag).
// R16: counter self-resets on the provably-last pop (drops the memset node).
// ---------------------------------------------------------------------------
#define NQT_    (T_/128)            // 16 q-tiles
#define NTILE_  (NQT_*B_*H_)        // 512 work items
#define AQ_B    18432               // Q region: 128*144
#define AT_T    9216                // one 64x144 tile
#define AT_STG2 (2*AT_T)            // K+V stage
#define AT_SMEM (AQ_B + 3*AT_STG2)  // 73728

__device__ __forceinline__ void attn_load_kv16(
    uint32_t sb, int k0, int tid,
    const __half* __restrict__ Kg, const __half* __restrict__ Vg)
{
#pragma unroll
    for (int p = 0; p < 2; p++) {
        int idx = tid + p * 256;    // 0..511
        int row = idx >> 3;         // 0..63
        int c8  = (idx & 7) * 8;
        cp16(sb + (uint32_t)(row * 144 + c8 * 2),        Kg + (size_t)(k0 + row) * 64 + c8);
        cp16(sb + (uint32_t)(AT_T + row * 144 + c8 * 2), Vg + (size_t)(k0 + row) * 64 + c8);
    }
}

__global__ void __launch_bounds__(256, 2) attn_f16_kernel(const float* __restrict__ rwr_alpha)
{
    extern __shared__ char smem[];
    __shared__ int s_tile;
    const uint32_t sbase = smem_u32(smem);
    const int tid  = threadIdx.x;
    const int wid  = tid >> 5;
    const int lane = tid & 31;

    const int lr = lane & 7, sel = lane >> 3;
    const int rowA = ((sel & 1) ? 8 : 0) + lr;
    const int kbA  = (sel & 2) ? 16 : 0;
    const int rowB = ((sel & 2) ? 8 : 0) + lr;
    const int kbB  = (sel & 1) ? 16 : 0;
    const int g  = lane >> 2;
    const int t2 = (lane & 3) * 2;
    const uint32_t ones = 0x3C003C00u;   // all-ones B frag: every col = rowsum

    for (;;) {
        __syncthreads();                 // prior tile fully done; s_tile free
        if (tid == 0) s_tile = atomicAdd(&g_ctr, 1);
        __syncthreads();
        const int idx = s_tile;
        if (idx >= NTILE_) {
            // pops are totally ordered; each of gridDim.x CTAs makes exactly
            // one failed pop, so idx == NTILE_+gridDim.x-1 is the LAST pop of
            // this launch -> safe to reset for the next graph replay.
            if (tid == 0 && idx == NTILE_ + (int)gridDim.x - 1)
                atomicExch(&g_ctr, 0);
            break;
        }

        // heavy-first: all 32 heads' qt=15 tiles, then qt=14, ...
        const int qt = (NQT_ - 1) - (idx >> 5);
        const int bh = idx & 31;
        const int q0 = qt * 128;
        const int qw = q0 + wid * 16;
        const int nkt = 2 * qt + 2;

        const size_t hoff = (size_t)bh * (T_ * D_);
        const __half* Qg = g_q16 + hoff;
        const __half* Kg = g_k16 + hoff;
        const __half* Vg = g_v16 + hoff;

        const int h = bh & (H_ - 1);
        const int b = bh >> 4;
        const float alpha = fminf(fmaxf(rwr_alpha[h], 0.0f), 0.5f);
        const float om = 1.0f - alpha;

        // Q tile load (group 0)
#pragma unroll
        for (int p = 0; p < 4; p++) {
            int i2 = tid + p * 256;
            int row = i2 >> 3;
            int c8  = (i2 & 7) * 8;
            cp16(sbase + (uint32_t)(row * 144 + c8 * 2), Qg + (size_t)(q0 + row) * 64 + c8);
        }
        asm volatile("cp.async.commit_group;" ::: "memory");

        attn_load_kv16(sbase + AQ_B,           0,  tid, Kg, Vg);
        asm volatile("cp.async.commit_group;" ::: "memory");
        attn_load_kv16(sbase + AQ_B + AT_STG2, 64, tid, Kg, Vg);
        asm volatile("cp.async.commit_group;" ::: "memory");

        asm volatile("cp.async.wait_group 2;" ::: "memory");
        __syncthreads();

        uint32_t qh[4][4];
        {
            const uint32_t qaddr = sbase + (uint32_t)((wid * 16 + rowA) * 144 + kbA);
#pragma unroll
            for (int kc = 0; kc < 4; kc++) ldsm4(qh[kc], qaddr + (uint32_t)(kc * 32));
        }

        float O[8][4];
        float Ol[4] = {0.0f, 0.0f, 0.0f, 0.0f};
        float mrow[2] = {-1e30f, -1e30f};
#pragma unroll
        for (int nt = 0; nt < 8; nt++)
#pragma unroll
            for (int c = 0; c < 4; c++) O[nt][c] = 0.0f;

        for (int kt = 0; kt < nkt; kt++) {
            if (kt + 1 < nkt) asm volatile("cp.async.wait_group 1;" ::: "memory");
            else              asm volatile("cp.async.wait_group 0;" ::: "memory");
            __syncthreads();
            if (kt + 2 < nkt) {
                attn_load_kv16(sbase + AQ_B + (uint32_t)((kt + 2) % 3) * AT_STG2,
                               (kt + 2) * 64, tid, Kg, Vg);
                asm volatile("cp.async.commit_group;" ::: "memory");
            }

            const uint32_t sb = sbase + AQ_B + (uint32_t)(kt % 3) * AT_STG2;
            const int k0 = kt * 64;

            if (k0 <= qw + 15) {
                // ---- S = Q.K^T (scores in log2 domain) ----
                float S[8][4];
#pragma unroll
                for (int nt = 0; nt < 8; nt++)
#pragma unroll
                    for (int c = 0; c < 4; c++) S[nt][c] = 0.0f;

#pragma unroll
                for (int np = 0; np < 4; np++) {
                    const uint32_t kb_ = sb + (uint32_t)((np * 16 + rowB) * 144 + kbB);
#pragma unroll
                    for (int kc = 0; kc < 4; kc++) {
                        uint32_t k4[4];
                        ldsm4(k4, kb_ + (uint32_t)(kc * 32));
                        mma_f16(S[2*np],     qh[kc], k4[0], k4[1]);
                        mma_f16(S[2*np + 1], qh[kc], k4[2], k4[3]);
                    }
                }

                // ---- causal mask ----
                if (k0 + 63 > qw) {
#pragma unroll
                    for (int nt = 0; nt < 8; nt++) {
                        const int colb = k0 + nt * 8 + t2;
#pragma unroll
                        for (int c = 0; c < 2; c++) {
                            if (colb + c > qw + g)     S[nt][c]     = -1e30f;
                            if (colb + c > qw + g + 8) S[nt][2 + c] = -1e30f;
                        }
                    }
                }

                // ---- row max + CONDITIONAL rescale ----
                float mn[2];
#pragma unroll
                for (int r = 0; r < 2; r++) {
                    float mx = -1e30f;
#pragma unroll
                    for (int nt = 0; nt < 8; nt++)
                        mx = fmaxf(mx, fmaxf(S[nt][2*r], S[nt][2*r + 1]));
                    mx = fmaxf(mx, __shfl_xor_sync(0xffffffffu, mx, 1));
                    mx = fmaxf(mx, __shfl_xor_sync(0xffffffffu, mx, 2));
                    mn[r] = fmaxf(mrow[r], mx);
                }
                // skip is EXACT when no row max rose (corr == ex2(0) == 1)
                if (__any_sync(0xffffffffu,
                               (mn[0] > mrow[0]) | (mn[1] > mrow[1]))) {
#pragma unroll
                    for (int r = 0; r < 2; r++) {
                        const float corr = ex2_(mrow[r] - mn[r]);
                        mrow[r] = mn[r];
#pragma unroll
                        for (int nt = 0; nt < 8; nt++) {
                            O[nt][2*r]     *= corr;
                            O[nt][2*r + 1] *= corr;
                        }
                        Ol[2*r] *= corr;
                    }
                }

                // ---- P = exp2(S - m) in f16x2 ----
                uint32_t pa[4][4];
#pragma unroll
                for (int kc = 0; kc < 4; kc++) {
                    pa[kc][0] = ex2h2_(packh2_(S[2*kc][0]   - mn[0], S[2*kc][1]   - mn[0]));
                    pa[kc][1] = ex2h2_(packh2_(S[2*kc][2]   - mn[1], S[2*kc][3]   - mn[1]));
                    pa[kc][2] = ex2h2_(packh2_(S[2*kc+1][0] - mn[0], S[2*kc+1][1] - mn[0]));
                    pa[kc][3] = ex2h2_(packh2_(S[2*kc+1][2] - mn[1], S[2*kc+1][3] - mn[1]));
                }

                // ---- O += P.V ; l += P.ones (same P, fp32 accum) ----
#pragma unroll
                for (int kc = 0; kc < 4; kc++) {
                    mma_f16(Ol, pa[kc], ones, ones);
#pragma unroll
                    for (int nd = 0; nd < 4; nd++) {
                        uint32_t v4[4];
                        const uint32_t vaddr = sb + (uint32_t)(AT_T
                            + (kc * 16 + (lane & 15)) * 144
                            + nd * 32 + ((lane & 16) ? 16 : 0));
                        ldsm4t(v4, vaddr);
                        mma_f16(O[2*nd],     pa[kc], v4[0], v4[1]);
                        mma_f16(O[2*nd + 1], pa[kc], v4[2], v4[3]);
                    }
                }
            }
        }

        // ---- epilogue: normalize, reciprocal mix, write y fp16 ----
#pragma unroll
        for (int r = 0; r < 2; r++) {
            const int q = qw + g + r * 8;
            const float inv = 1.0f / Ol[2*r];
            const size_t vrow = (size_t)q * 64;
            const size_t orow = ((size_t)(b * T_ + q)) * C_ + h * 64;
#pragma unroll
            for (int nt = 0; nt < 8; nt++) {
                const int d = nt * 8 + t2;
                const uint32_t uv = *(const uint32_t*)&Vg[vrow + d];
                const float2 fv = __half22float2(*(const __half2*)&uv);
                const float y0 = om * (O[nt][2*r]     * inv) + alpha * fv.x;
                const float y1 = om * (O[nt][2*r + 1] * inv) + alpha * fv.y;
                *(uint32_t*)&g_y16[orow + d] = packh2_(y0, y1);
            }
        }
    }
}

// ---------------------------------------------------------------------------
extern "C" void kernel_launch(void* const* d_in, const int* in_sizes, int n_in,
                              void* d_out, int out_size)
{
    const float* x         = (const float*)d_in[0];
    const float* W_attn    = (const float*)d_in[1];
    const float* W_proj    = (const float*)d_in[2];
    const float* w_std     = (const float*)d_in[3];
    const float* w_rec     = (const float*)d_in[4];
    const float* skip_std  = (const float*)d_in[5];
    const float* skip_low  = (const float*)d_in[6];
    const float* rwr_alpha = (const float*)d_in[7];
    float* out = (float*)d_out;

    static void *p_x16 = nullptr, *p_wa16, *p_wp16, *p_y16;
    if (!p_x16) {
        cudaGetSymbolAddress(&p_x16,  g_x16);
        cudaGetSymbolAddress(&p_wa16, g_wa16);
        cudaGetSymbolAddress(&p_wp16, g_wp16);
        cudaGetSymbolAddress(&p_y16,  g_y16);
    }

    static bool attr_set = false;
    if (!attr_set) {
        cudaFuncSetAttribute(gemm_f16_kernel, cudaFuncAttributeMaxDynamicSharedMemorySize, GS_SMEM);
        cudaFuncSetAttribute(attn_f16_kernel, cudaFuncAttributeMaxDynamicSharedMemorySize, AT_SMEM);
        attr_set = true;
    }

    // 1. fused fp32 -> fp16 conversion (grid-stride, high MLP)
    conv_kernel<<<CONV_BLOCKS, 256>>>(
        (const float4*)x, (const float4*)W_attn, (const float4*)W_proj);

    // 2. QKV GEMM -> q/k/v fp16 with head scaling (+ log2e fold for q,k)
    gemm_f16_kernel<<<dim3(3*C_/128, M_/128), 128, GS_SMEM>>>(
        (const __half*)p_x16, (const __half*)p_wa16,
        nullptr, 3*C_, C_, 0, w_std, w_rec, skip_std, skip_low);

    // 3. attention: persistent 296-CTA grid, heavy-first atomic work queue
    //    (counter self-resets on the last pop; no memset node needed)
    attn_f16_kernel<<<296, 256, AT_SMEM>>>(rwr_alpha);

    // 4. output projection -> fp32 out
    gemm_f16_kernel<<<dim3(C_/128, M_/128), 128, GS_SMEM>>>(
        (const __half*)p_y16, (const __half*)p_wp16,
        out, C_, C_, 1, nullptr, nullptr, nullptr, nullptr);
}